// round 3
// baseline (speedup 1.0000x reference)
#include <cuda_runtime.h>
#include <math_constants.h>

#define NQ      1024
#define LEN     50
#define NJ      974      // NQ - LEN
#define NK      100
#define KT      5        // shapelets per block
#define NTHR    256
#define JJ      4        // ceil(NJ / NTHR)
#define ALPHA_F (-100.0f)

__global__ __launch_bounds__(NTHR, 2)
void softmin_shapelet_kernel(const float* __restrict__ x,
                             const float* __restrict__ s,
                             float* __restrict__ out)
{
    __shared__ __align__(16) float xs[NQ + 4];      // padded row of x
    __shared__ __align__(16) float ss[KT][52];      // shapelets, padded to 52
    __shared__ float ssq_sh[KT];
    __shared__ float redmin[8][KT];
    __shared__ float redsum[8][KT][2];

    const int t    = threadIdx.x;
    const int n    = blockIdx.y;
    const int kt   = blockIdx.x;
    const int k0   = kt * KT;
    const int warp = t >> 5;
    const int lane = t & 31;

    // ---- stage x row (float4) ----
    {
        const float4* xg  = (const float4*)(x + (size_t)n * NQ);
        float4*       xs4 = (float4*)xs;
        for (int i = t; i < NQ / 4; i += NTHR) xs4[i] = xg[i];
        if (t < 4) xs[NQ + t] = 0.0f;   // pad so window reads up to xs[NJ-1+51] are safe
    }
    // ---- stage shapelet tile, zero-padded to 52 ----
    for (int i = t; i < KT * 52; i += NTHR) {
        int k = i / 52, l = i - k * 52;
        ((float*)ss)[i] = (l < LEN) ? s[(size_t)(k0 + k) * LEN + l] : 0.0f;
    }
    __syncthreads();

    if (t < KT) {
        float a = 0.0f;
        #pragma unroll
        for (int l = 0; l < LEN; l++) a = fmaf(ss[t][l], ss[t][l], a);
        ssq_sh[t] = a;
    }
    __syncthreads();

    float ssq[KT];
    #pragma unroll
    for (int k = 0; k < KT; k++) ssq[k] = ssq_sh[k];

    // ---- compute D for this thread's JJ window positions ----
    float Dreg[JJ * KT];

    #pragma unroll
    for (int jj = 0; jj < JJ; jj++) {
        int  j     = t + jj * NTHR;
        bool valid = (j < NJ);
        int  jb    = valid ? j : 0;

        float wv[52];
        #pragma unroll
        for (int l = 0; l < 52; l++) wv[l] = xs[jb + l];

        float sq = 0.0f;
        #pragma unroll
        for (int l = 0; l < LEN; l++) sq = fmaf(wv[l], wv[l], sq);

        #pragma unroll
        for (int k = 0; k < KT; k++) {
            const float4* s4 = (const float4*)ss[k];
            float acc = 0.0f;
            #pragma unroll
            for (int l4 = 0; l4 < 13; l4++) {
                float4 v = s4[l4];
                acc = fmaf(wv[4 * l4 + 0], v.x, acc);
                acc = fmaf(wv[4 * l4 + 1], v.y, acc);
                acc = fmaf(wv[4 * l4 + 2], v.z, acc);
                acc = fmaf(wv[4 * l4 + 3], v.w, acc);
            }
            float D = (sq - 2.0f * acc + ssq[k]) * (1.0f / (float)LEN);
            Dreg[jj * KT + k] = valid ? D : CUDART_INF_F;
        }
    }

    // ---- block min over j, per k ----
    float m[KT];
    #pragma unroll
    for (int k = 0; k < KT; k++) {
        float mv = Dreg[k];
        #pragma unroll
        for (int jj = 1; jj < JJ; jj++) mv = fminf(mv, Dreg[jj * KT + k]);
        #pragma unroll
        for (int off = 16; off > 0; off >>= 1)
            mv = fminf(mv, __shfl_xor_sync(0xFFFFFFFFu, mv, off));
        m[k] = mv;
    }
    if (lane == 0) {
        #pragma unroll
        for (int k = 0; k < KT; k++) redmin[warp][k] = m[k];
    }
    __syncthreads();

    float gmin[KT];
    #pragma unroll
    for (int k = 0; k < KT; k++) {
        float mv = redmin[0][k];
        #pragma unroll
        for (int w = 1; w < 8; w++) mv = fminf(mv, redmin[w][k]);
        gmin[k] = mv;
    }

    // ---- softmin sums ----
    float sw[KT], swd[KT];
    #pragma unroll
    for (int k = 0; k < KT; k++) { sw[k] = 0.0f; swd[k] = 0.0f; }

    #pragma unroll
    for (int jj = 0; jj < JJ; jj++) {
        int j = t + jj * NTHR;
        if (j < NJ) {
            #pragma unroll
            for (int k = 0; k < KT; k++) {
                float d = Dreg[jj * KT + k] - gmin[k];
                float w = __expf(ALPHA_F * d);
                sw[k]  += w;
                swd[k] = fmaf(w, d, swd[k]);
            }
        }
    }

    #pragma unroll
    for (int k = 0; k < KT; k++) {
        #pragma unroll
        for (int off = 16; off > 0; off >>= 1) {
            sw[k]  += __shfl_xor_sync(0xFFFFFFFFu, sw[k],  off);
            swd[k] += __shfl_xor_sync(0xFFFFFFFFu, swd[k], off);
        }
    }
    if (lane == 0) {
        #pragma unroll
        for (int k = 0; k < KT; k++) {
            redsum[warp][k][0] = sw[k];
            redsum[warp][k][1] = swd[k];
        }
    }
    __syncthreads();

    if (t < KT) {
        float SW = 0.0f, SWD = 0.0f;
        #pragma unroll
        for (int w = 0; w < 8; w++) {
            SW  += redsum[w][t][0];
            SWD += redsum[w][t][1];
        }
        out[(size_t)n * NK + k0 + t] = SWD / SW;
    }
}

extern "C" void kernel_launch(void* const* d_in, const int* in_sizes, int n_in,
                              void* d_out, int out_size)
{
    const float* x = (const float*)d_in[0];   // (512, 1024)
    const float* s = (const float*)d_in[1];   // (100, 50)
    float* out = (float*)d_out;               // (512, 100)

    dim3 grid(NK / KT, 512);                  // (20, 512)
    softmin_shapelet_kernel<<<grid, NTHR>>>(x, s, out);
}

// round 4
// speedup vs baseline: 1.9804x; 1.9804x over previous
#include <cuda_runtime.h>
#include <math_constants.h>

#define NQ      1024
#define LEN     50
#define NJ      974      // NQ - LEN
#define NK      100
#define KT      5        // shapelets per block
#define NTHR    256
#define RJ      4        // consecutive j per thread -> 1024 positions covered
#define NCHUNK  13       // 52 padded l-steps / 4
#define ALPHA_F (-100.0f)

__global__ __launch_bounds__(NTHR, 3)
void softmin_shapelet_kernel(const float* __restrict__ x,
                             const float* __restrict__ s,
                             float* __restrict__ out)
{
    __shared__ __align__(16) float xs[NQ + 64];     // padded row of x
    __shared__ __align__(16) float ss[KT][52];      // shapelets, zero-padded to 52
    __shared__ float ssq_sh[KT];
    __shared__ float redmin[8][KT];
    __shared__ float redsum[8][KT][2];

    const int t    = threadIdx.x;
    const int n    = blockIdx.y;
    const int k0   = blockIdx.x * KT;
    const int warp = t >> 5;
    const int lane = t & 31;

    // ---- stage x row (float4) + zero pad ----
    {
        const float4* xg  = (const float4*)(x + (size_t)n * NQ);
        float4*       xs4 = (float4*)xs;
        for (int i = t; i < NQ / 4; i += NTHR) xs4[i] = xg[i];
        if (t < 16) xs4[NQ / 4 + t] = make_float4(0.f, 0.f, 0.f, 0.f);
    }
    // ---- stage shapelet tile, zero-padded to 52 ----
    for (int i = t; i < KT * 52; i += NTHR) {
        int k = i / 52, l = i - k * 52;
        ((float*)ss)[i] = (l < LEN) ? s[(size_t)(k0 + k) * LEN + l] : 0.0f;
    }
    __syncthreads();

    if (t < KT) {
        float a = 0.0f;
        #pragma unroll
        for (int l = 0; l < LEN; l++) a = fmaf(ss[t][l], ss[t][l], a);
        ssq_sh[t] = a;
    }
    __syncthreads();

    // ---- rolling-window cross-correlation ----
    // Thread t owns j = 4t .. 4t+3 (consecutive). Per 4-l chunk:
    //   1 LDS.128 of x (4 new values, 7 live), 5 LDS.128 of s, 80 cross FMA + sq FMA.
    float acc[RJ][KT];
    float sq[RJ];
    #pragma unroll
    for (int jj = 0; jj < RJ; jj++) {
        sq[jj] = 0.0f;
        #pragma unroll
        for (int k = 0; k < KT; k++) acc[jj][k] = 0.0f;
    }

    const float4* xs4 = (const float4*)xs;
    float4 cur = xs4[t];                       // xs[4t .. 4t+3]
    #pragma unroll
    for (int c = 0; c < NCHUNK; c++) {
        float4 nxt = xs4[t + c + 1];           // xs[4t+4c+4 .. +7]
        float xv[7] = {cur.x, cur.y, cur.z, cur.w, nxt.x, nxt.y, nxt.z};
        float sv[KT][4];
        #pragma unroll
        for (int k = 0; k < KT; k++) {
            float4 v = ((const float4*)ss[k])[c];
            sv[k][0] = v.x; sv[k][1] = v.y; sv[k][2] = v.z; sv[k][3] = v.w;
        }
        #pragma unroll
        for (int dl = 0; dl < 4; dl++) {
            const int l = 4 * c + dl;          // compile-time after unroll
            #pragma unroll
            for (int jj = 0; jj < RJ; jj++) {
                float xval = xv[jj + dl];      // constant index -> register
                if (l < LEN) sq[jj] = fmaf(xval, xval, sq[jj]);
                #pragma unroll
                for (int k = 0; k < KT; k++)
                    acc[jj][k] = fmaf(xval, sv[k][dl], acc[jj][k]);
            }
        }
        cur = nxt;
    }

    // ---- form D in-place (acc -> D), mask invalid j with +inf ----
    #pragma unroll
    for (int jj = 0; jj < RJ; jj++) {
        const int  j     = RJ * t + jj;
        const bool valid = (j < NJ);
        #pragma unroll
        for (int k = 0; k < KT; k++) {
            float D = (sq[jj] - 2.0f * acc[jj][k] + ssq_sh[k]) * (1.0f / (float)LEN);
            acc[jj][k] = valid ? D : CUDART_INF_F;
        }
    }

    // ---- block min over j, per k ----
    float gmin[KT];
    #pragma unroll
    for (int k = 0; k < KT; k++) {
        float mv = acc[0][k];
        #pragma unroll
        for (int jj = 1; jj < RJ; jj++) mv = fminf(mv, acc[jj][k]);
        #pragma unroll
        for (int off = 16; off > 0; off >>= 1)
            mv = fminf(mv, __shfl_xor_sync(0xFFFFFFFFu, mv, off));
        if (lane == 0) redmin[warp][k] = mv;
    }
    __syncthreads();
    #pragma unroll
    for (int k = 0; k < KT; k++) {
        float mv = redmin[0][k];
        #pragma unroll
        for (int w = 1; w < 8; w++) mv = fminf(mv, redmin[w][k]);
        gmin[k] = mv;
    }

    // ---- softmin sums ----
    float sw[KT], swd[KT];
    #pragma unroll
    for (int k = 0; k < KT; k++) { sw[k] = 0.0f; swd[k] = 0.0f; }

    #pragma unroll
    for (int jj = 0; jj < RJ; jj++) {
        const int j = RJ * t + jj;
        if (j < NJ) {
            #pragma unroll
            for (int k = 0; k < KT; k++) {
                float d = acc[jj][k] - gmin[k];
                float w = __expf(ALPHA_F * d);
                sw[k]  += w;
                swd[k]  = fmaf(w, d, swd[k]);
            }
        }
    }

    #pragma unroll
    for (int k = 0; k < KT; k++) {
        #pragma unroll
        for (int off = 16; off > 0; off >>= 1) {
            sw[k]  += __shfl_xor_sync(0xFFFFFFFFu, sw[k],  off);
            swd[k] += __shfl_xor_sync(0xFFFFFFFFu, swd[k], off);
        }
        if (lane == 0) { redsum[warp][k][0] = sw[k]; redsum[warp][k][1] = swd[k]; }
    }
    __syncthreads();

    if (t < KT) {
        float SW = 0.0f, SWD = 0.0f;
        #pragma unroll
        for (int w = 0; w < 8; w++) {
            SW  += redsum[w][t][0];
            SWD += redsum[w][t][1];
        }
        out[(size_t)n * NK + k0 + t] = SWD / SW;
    }
}

extern "C" void kernel_launch(void* const* d_in, const int* in_sizes, int n_in,
                              void* d_out, int out_size)
{
    const float* x = (const float*)d_in[0];   // (512, 1024)
    const float* s = (const float*)d_in[1];   // (100, 50)
    float* out = (float*)d_out;               // (512, 100)

    dim3 grid(NK / KT, 512);                  // (20, 512)
    softmin_shapelet_kernel<<<grid, NTHR>>>(x, s, out);
}

// round 6
// speedup vs baseline: 2.3681x; 1.1958x over previous
#include <cuda_runtime.h>
#include <math_constants.h>

#define NQ      1024
#define LEN     50
#define NJ      974      // NQ - LEN
#define NK      100
#define KT      5        // shapelets per block
#define NTHR    128
#define RJ      8        // consecutive j per thread -> 1024 positions covered
#define NJP     4        // RJ/2 packed j-pairs
#define NCHUNK  13       // 52 padded l-steps / 4
#define NWARP   4
#define ALPHA_F (-100.0f)

__device__ __forceinline__ unsigned long long pack2(float lo, float hi) {
    unsigned long long r;
    asm("mov.b64 %0, {%1, %2};" : "=l"(r) : "f"(lo), "f"(hi));
    return r;
}
__device__ __forceinline__ void unpack2(unsigned long long v, float& lo, float& hi) {
    asm("mov.b64 {%0, %1}, %2;" : "=f"(lo), "=f"(hi) : "l"(v));
}
// d = a*b + d, two packed fp32 lanes
__device__ __forceinline__ void ffma2(unsigned long long& d,
                                      unsigned long long a, unsigned long long b) {
    asm("fma.rn.f32x2 %0, %1, %2, %0;" : "+l"(d) : "l"(a), "l"(b));
}

__global__ __launch_bounds__(NTHR, 4)
void softmin_shapelet_kernel(const float* __restrict__ x,
                             const float* __restrict__ s,
                             float* __restrict__ out)
{
    __shared__ __align__(16) float  xs[NQ + 64];     // x row + zero pad
    __shared__ __align__(16) float2 ss2[KT][52];     // shapelets duplicated {s,s}, zero-padded
    __shared__ float ssq_sh[KT];
    __shared__ float redmin[NWARP][KT];
    __shared__ float redsum[NWARP][KT][2];

    const int t    = threadIdx.x;
    const int n    = blockIdx.y;
    const int k0   = blockIdx.x * KT;
    const int warp = t >> 5;
    const int lane = t & 31;

    // ---- stage x row (float4) + zero pad ----
    {
        const float4* xg  = (const float4*)(x + (size_t)n * NQ);
        float4*       xs4 = (float4*)xs;
        #pragma unroll
        for (int i = t; i < NQ / 4; i += NTHR) xs4[i] = xg[i];
        if (t < 16) xs4[NQ / 4 + t] = make_float4(0.f, 0.f, 0.f, 0.f);
    }
    // ---- stage shapelet tile, duplicated to {v,v}, zero-padded to 52 ----
    for (int i = t; i < KT * 52; i += NTHR) {
        int k = i / 52, l = i - k * 52;
        float v = (l < LEN) ? s[(size_t)(k0 + k) * LEN + l] : 0.0f;
        ss2[k][l] = make_float2(v, v);
    }
    __syncthreads();

    if (t < KT) {
        float a = 0.0f;
        #pragma unroll
        for (int l = 0; l < LEN; l++) { float v = ss2[t][l].x; a = fmaf(v, v, a); }
        ssq_sh[t] = a;
    }
    __syncthreads();

    // ---- rolling-window cross-correlation, j-pair packed FFMA2 ----
    // Thread t owns j = 8t .. 8t+7 (4 packed pairs).
    unsigned long long acc2[NJP][KT];
    unsigned long long sq2[NJP];
    #pragma unroll
    for (int jp = 0; jp < NJP; jp++) {
        sq2[jp] = 0ull;
        #pragma unroll
        for (int k = 0; k < KT; k++) acc2[jp][k] = 0ull;
    }

    const float4* xs4 = (const float4*)xs;
    float4 c0 = xs4[2 * t];
    float4 c1 = xs4[2 * t + 1];
    #pragma unroll
    for (int c = 0; c < NCHUNK; c++) {
        float4 nx = xs4[2 * t + c + 2];
        float xv[11] = {c0.x, c0.y, c0.z, c0.w,
                        c1.x, c1.y, c1.z, c1.w,
                        nx.x, nx.y, nx.z};
        unsigned long long P[10];
        #pragma unroll
        for (int m = 0; m < 10; m++) P[m] = pack2(xv[m], xv[m + 1]);

        #pragma unroll
        for (int k = 0; k < KT; k++) {
            const ulonglong2* sp = (const ulonglong2*)(ss2[k]);  // each elem = 2 packed {s,s}
            ulonglong2 pa = sp[2 * c];       // l = 4c, 4c+1
            ulonglong2 pb = sp[2 * c + 1];   // l = 4c+2, 4c+3
            unsigned long long sd0 = pa.x, sd1 = pa.y, sd2 = pb.x, sd3 = pb.y;
            #pragma unroll
            for (int jp = 0; jp < NJP; jp++) {
                ffma2(acc2[jp][k], P[2 * jp + 0], sd0);
                ffma2(acc2[jp][k], P[2 * jp + 1], sd1);
                ffma2(acc2[jp][k], P[2 * jp + 2], sd2);
                ffma2(acc2[jp][k], P[2 * jp + 3], sd3);
            }
        }
        // sq-window accumulation: ONLY for real l < LEN (chunk 12 covers l=48..51,
        // of which l=50,51 are padding -> static guard, zero cost after unroll)
        #pragma unroll
        for (int dl = 0; dl < 4; dl++) {
            if (4 * c + dl < LEN) {
                #pragma unroll
                for (int jp = 0; jp < NJP; jp++)
                    ffma2(sq2[jp], P[2 * jp + dl], P[2 * jp + dl]);
            }
        }
        c0 = c1; c1 = nx;
    }

    // ---- pass 1: block min over j, per k (D recomputed from packed accs) ----
    float gmin[KT];
    {
        float m[KT];
        #pragma unroll
        for (int k = 0; k < KT; k++) m[k] = CUDART_INF_F;
        #pragma unroll
        for (int jp = 0; jp < NJP; jp++) {
            float sqa, sqb;
            unpack2(sq2[jp], sqa, sqb);
            const int  ja = RJ * t + 2 * jp, jb = ja + 1;
            const bool va = (ja < NJ), vb = (jb < NJ);
            #pragma unroll
            for (int k = 0; k < KT; k++) {
                float ca, cb;
                unpack2(acc2[jp][k], ca, cb);
                float Da = (sqa - 2.0f * ca + ssq_sh[k]) * (1.0f / (float)LEN);
                float Db = (sqb - 2.0f * cb + ssq_sh[k]) * (1.0f / (float)LEN);
                if (va) m[k] = fminf(m[k], Da);
                if (vb) m[k] = fminf(m[k], Db);
            }
        }
        #pragma unroll
        for (int k = 0; k < KT; k++) {
            #pragma unroll
            for (int off = 16; off > 0; off >>= 1)
                m[k] = fminf(m[k], __shfl_xor_sync(0xFFFFFFFFu, m[k], off));
            if (lane == 0) redmin[warp][k] = m[k];
        }
        __syncthreads();
        #pragma unroll
        for (int k = 0; k < KT; k++) {
            float mv = redmin[0][k];
            #pragma unroll
            for (int w = 1; w < NWARP; w++) mv = fminf(mv, redmin[w][k]);
            gmin[k] = mv;
        }
    }

    // ---- pass 2: softmin sums ----
    float sw[KT], swd[KT];
    #pragma unroll
    for (int k = 0; k < KT; k++) { sw[k] = 0.0f; swd[k] = 0.0f; }

    #pragma unroll
    for (int jp = 0; jp < NJP; jp++) {
        float sqa, sqb;
        unpack2(sq2[jp], sqa, sqb);
        const int  ja = RJ * t + 2 * jp, jb = ja + 1;
        const bool va = (ja < NJ), vb = (jb < NJ);
        #pragma unroll
        for (int k = 0; k < KT; k++) {
            float ca, cb;
            unpack2(acc2[jp][k], ca, cb);
            if (va) {
                float d = (sqa - 2.0f * ca + ssq_sh[k]) * (1.0f / (float)LEN) - gmin[k];
                float w = __expf(ALPHA_F * d);
                sw[k] += w; swd[k] = fmaf(w, d, swd[k]);
            }
            if (vb) {
                float d = (sqb - 2.0f * cb + ssq_sh[k]) * (1.0f / (float)LEN) - gmin[k];
                float w = __expf(ALPHA_F * d);
                sw[k] += w; swd[k] = fmaf(w, d, swd[k]);
            }
        }
    }

    #pragma unroll
    for (int k = 0; k < KT; k++) {
        #pragma unroll
        for (int off = 16; off > 0; off >>= 1) {
            sw[k]  += __shfl_xor_sync(0xFFFFFFFFu, sw[k],  off);
            swd[k] += __shfl_xor_sync(0xFFFFFFFFu, swd[k], off);
        }
        if (lane == 0) { redsum[warp][k][0] = sw[k]; redsum[warp][k][1] = swd[k]; }
    }
    __syncthreads();

    if (t < KT) {
        float SW = 0.0f, SWD = 0.0f;
        #pragma unroll
        for (int w = 0; w < NWARP; w++) {
            SW  += redsum[w][t][0];
            SWD += redsum[w][t][1];
        }
        out[(size_t)n * NK + k0 + t] = SWD / SW;
    }
}

extern "C" void kernel_launch(void* const* d_in, const int* in_sizes, int n_in,
                              void* d_out, int out_size)
{
    const float* x = (const float*)d_in[0];   // (512, 1024)
    const float* s = (const float*)d_in[1];   // (100, 50)
    float* out = (float*)d_out;               // (512, 100)

    dim3 grid(NK / KT, 512);                  // (20, 512)
    softmin_shapelet_kernel<<<grid, NTHR>>>(x, s, out);
}

// round 7
// speedup vs baseline: 3.3507x; 1.4150x over previous
#include <cuda_runtime.h>
#include <math_constants.h>

#define NQ      1024
#define LEN     50
#define NJ      974      // NQ - LEN
#define NK      100
#define KT      4        // shapelets per block (2 packed pairs)
#define KTP     2        // k-pairs
#define NTHR    128
#define RJ      8        // consecutive j per thread -> 1024 positions
#define NCHUNK  13       // 52 padded l-steps / 4
#define NWARP   4
#define ALPHA_F (-100.0f)
#define INV_LEN (1.0f / 50.0f)

__device__ __forceinline__ void unpack2(unsigned long long v, float& lo, float& hi) {
    asm("mov.b64 {%0, %1}, %2;" : "=f"(lo), "=f"(hi) : "l"(v));
}
// d = a*b + d, two packed fp32 lanes
__device__ __forceinline__ void ffma2(unsigned long long& d,
                                      unsigned long long a, unsigned long long b) {
    asm("fma.rn.f32x2 %0, %1, %2, %0;" : "+l"(d) : "l"(a), "l"(b));
}

__global__ __launch_bounds__(NTHR, 4)
void softmin_shapelet_kernel(const float* __restrict__ x,
                             const float* __restrict__ s,
                             float* __restrict__ out)
{
    __shared__ __align__(16) float2 dup[1088];        // {x[m], x[m]} duplicated, zero-padded
    __shared__ __align__(16) float  csA[1088];        // csA[m] = csum[m+1] (cumsum of x^2)
    __shared__ __align__(16) float2 spair[KTP][56];   // {s_2kp[l], s_2kp+1[l]}, zero-padded
    __shared__ float ssq_sh[KT];
    __shared__ float warpsum[NWARP];
    __shared__ float redmin[NWARP][KT];
    __shared__ float redsum[NWARP][KT][2];

    const int t    = threadIdx.x;
    const int n    = blockIdx.y;
    const int k0   = blockIdx.x * KT;
    const int warp = t >> 5;
    const int lane = t & 31;

    // ---- stage x: load 8 values, write duplicated pairs ----
    const float4* xg = (const float4*)(x + (size_t)n * NQ);
    float4 a0 = xg[2 * t], a1 = xg[2 * t + 1];
    float v[8] = {a0.x, a0.y, a0.z, a0.w, a1.x, a1.y, a1.z, a1.w};

    float4* dup4 = (float4*)dup;
    #pragma unroll
    for (int q = 0; q < 4; q++)
        dup4[4 * t + q] = make_float4(v[2 * q], v[2 * q], v[2 * q + 1], v[2 * q + 1]);
    if (t < 32) dup4[512 + t] = make_float4(0.f, 0.f, 0.f, 0.f);      // dup[1024..1087]
    if (t < 16) ((float4*)csA)[256 + t] = make_float4(0.f, 0.f, 0.f, 0.f); // csA[1024..1087]

    // ---- stage shapelet k-pairs, zero-padded ----
    for (int i = t; i < KTP * 56; i += NTHR) {
        int kp = i / 56, l = i - kp * 56;
        float va = (l < LEN) ? s[(size_t)(k0 + 2 * kp)     * LEN + l] : 0.0f;
        float vb = (l < LEN) ? s[(size_t)(k0 + 2 * kp + 1) * LEN + l] : 0.0f;
        spair[kp][l] = make_float2(va, vb);
    }

    // ---- per-thread prefix of x^2, then block scan ----
    float p[8];
    p[0] = v[0] * v[0];
    #pragma unroll
    for (int i = 1; i < 8; i++) p[i] = fmaf(v[i], v[i], p[i - 1]);
    float tot = p[7], inc = tot;
    #pragma unroll
    for (int off = 1; off < 32; off <<= 1) {
        float o = __shfl_up_sync(0xFFFFFFFFu, inc, off);
        if (lane >= off) inc += o;
    }
    if (lane == 31) warpsum[warp] = inc;
    __syncthreads();

    float base = 0.0f;
    #pragma unroll
    for (int w = 0; w < NWARP; w++) if (w < warp) base += warpsum[w];
    const float ex = base + inc - tot;               // csum at position 8t
    ((float4*)csA)[2 * t]     = make_float4(ex + p[0], ex + p[1], ex + p[2], ex + p[3]);
    ((float4*)csA)[2 * t + 1] = make_float4(ex + p[4], ex + p[5], ex + p[6], ex + p[7]);

    if (t < KT) {                                    // shapelet self-energy
        const int kp = t >> 1, comp = t & 1;
        float aq = 0.0f;
        #pragma unroll
        for (int l = 0; l < LEN; l++) {
            float sv = comp ? spair[kp][l].y : spair[kp][l].x;
            aq = fmaf(sv, sv, aq);
        }
        ssq_sh[t] = aq;
    }
    __syncthreads();

    // ---- mainloop: all operands are aligned 64-bit SMEM pairs, zero packing ----
    unsigned long long acc2[RJ][KTP];
    #pragma unroll
    for (int jj = 0; jj < RJ; jj++)
        #pragma unroll
        for (int kp = 0; kp < KTP; kp++) acc2[jj][kp] = 0ull;

    const ulonglong2* dup2 = (const ulonglong2*)dup;
    unsigned long long d[12];                        // dup[8t+4c .. 8t+4c+11]
    {
        ulonglong2 q0 = dup2[4 * t + 0], q1 = dup2[4 * t + 1], q2 = dup2[4 * t + 2];
        ulonglong2 q3 = dup2[4 * t + 3], q4 = dup2[4 * t + 4], q5 = dup2[4 * t + 5];
        d[0] = q0.x; d[1]  = q0.y; d[2]  = q1.x; d[3]  = q1.y;
        d[4] = q2.x; d[5]  = q2.y; d[6]  = q3.x; d[7]  = q3.y;
        d[8] = q4.x; d[9]  = q4.y; d[10] = q5.x; d[11] = q5.y;
    }

    #pragma unroll
    for (int c = 0; c < NCHUNK; c++) {
        unsigned long long sd[KTP][4];
        #pragma unroll
        for (int kp = 0; kp < KTP; kp++) {
            const ulonglong2* sp = (const ulonglong2*)spair[kp];
            ulonglong2 pa = sp[2 * c], pb = sp[2 * c + 1];
            sd[kp][0] = pa.x; sd[kp][1] = pa.y; sd[kp][2] = pb.x; sd[kp][3] = pb.y;
        }
        #pragma unroll
        for (int dl = 0; dl < 4; dl++)
            #pragma unroll
            for (int jj = 0; jj < RJ; jj++)
                #pragma unroll
                for (int kp = 0; kp < KTP; kp++)
                    ffma2(acc2[jj][kp], d[jj + dl], sd[kp][dl]);
        if (c < NCHUNK - 1) {
            #pragma unroll
            for (int i = 0; i < 8; i++) d[i] = d[i + 4];
            ulonglong2 qa = dup2[4 * t + 2 * c + 6], qb = dup2[4 * t + 2 * c + 7];
            d[8] = qa.x; d[9] = qa.y; d[10] = qb.x; d[11] = qb.y;
        }
    }

    // ---- sq_win from cumsum ----
    float sq[RJ];
    #pragma unroll
    for (int i = 0; i < RJ; i++) {
        float ce = csA[8 * t + 49 + i];              // csum[8t+i+50]
        float cs = (i == 0) ? ex : ex + p[i - 1];    // csum[8t+i]  (own registers)
        sq[i] = ce - cs;
    }

    // ---- pass 1: block min per k ----
    float gmin[KT];
    {
        float m[KT];
        #pragma unroll
        for (int k = 0; k < KT; k++) m[k] = CUDART_INF_F;
        #pragma unroll
        for (int jj = 0; jj < RJ; jj++) {
            if (8 * t + jj < NJ) {
                #pragma unroll
                for (int kp = 0; kp < KTP; kp++) {
                    float ca, cb;
                    unpack2(acc2[jj][kp], ca, cb);
                    float Da = (sq[jj] - 2.0f * ca + ssq_sh[2 * kp])     * INV_LEN;
                    float Db = (sq[jj] - 2.0f * cb + ssq_sh[2 * kp + 1]) * INV_LEN;
                    m[2 * kp]     = fminf(m[2 * kp],     Da);
                    m[2 * kp + 1] = fminf(m[2 * kp + 1], Db);
                }
            }
        }
        #pragma unroll
        for (int k = 0; k < KT; k++) {
            #pragma unroll
            for (int off = 16; off > 0; off >>= 1)
                m[k] = fminf(m[k], __shfl_xor_sync(0xFFFFFFFFu, m[k], off));
            if (lane == 0) redmin[warp][k] = m[k];
        }
        __syncthreads();
        #pragma unroll
        for (int k = 0; k < KT; k++) {
            float mv = redmin[0][k];
            #pragma unroll
            for (int w = 1; w < NWARP; w++) mv = fminf(mv, redmin[w][k]);
            gmin[k] = mv;
        }
    }

    // ---- pass 2: softmin sums ----
    float sw[KT], swd[KT];
    #pragma unroll
    for (int k = 0; k < KT; k++) { sw[k] = 0.0f; swd[k] = 0.0f; }

    #pragma unroll
    for (int jj = 0; jj < RJ; jj++) {
        if (8 * t + jj < NJ) {
            #pragma unroll
            for (int kp = 0; kp < KTP; kp++) {
                float ca, cb;
                unpack2(acc2[jj][kp], ca, cb);
                {
                    float dd = (sq[jj] - 2.0f * ca + ssq_sh[2 * kp]) * INV_LEN - gmin[2 * kp];
                    float w  = __expf(ALPHA_F * dd);
                    sw[2 * kp] += w; swd[2 * kp] = fmaf(w, dd, swd[2 * kp]);
                }
                {
                    float dd = (sq[jj] - 2.0f * cb + ssq_sh[2 * kp + 1]) * INV_LEN - gmin[2 * kp + 1];
                    float w  = __expf(ALPHA_F * dd);
                    sw[2 * kp + 1] += w; swd[2 * kp + 1] = fmaf(w, dd, swd[2 * kp + 1]);
                }
            }
        }
    }

    #pragma unroll
    for (int k = 0; k < KT; k++) {
        #pragma unroll
        for (int off = 16; off > 0; off >>= 1) {
            sw[k]  += __shfl_xor_sync(0xFFFFFFFFu, sw[k],  off);
            swd[k] += __shfl_xor_sync(0xFFFFFFFFu, swd[k], off);
        }
        if (lane == 0) { redsum[warp][k][0] = sw[k]; redsum[warp][k][1] = swd[k]; }
    }
    __syncthreads();

    if (t < KT) {
        float SW = 0.0f, SWD = 0.0f;
        #pragma unroll
        for (int w = 0; w < NWARP; w++) {
            SW  += redsum[w][t][0];
            SWD += redsum[w][t][1];
        }
        out[(size_t)n * NK + k0 + t] = SWD / SW;
    }
}

extern "C" void kernel_launch(void* const* d_in, const int* in_sizes, int n_in,
                              void* d_out, int out_size)
{
    const float* x = (const float*)d_in[0];   // (512, 1024)
    const float* s = (const float*)d_in[1];   // (100, 50)
    float* out = (float*)d_out;               // (512, 100)

    dim3 grid(NK / KT, 512);                  // (25, 512)
    softmin_shapelet_kernel<<<grid, NTHR>>>(x, s, out);
}

// round 8
// speedup vs baseline: 3.5135x; 1.0486x over previous
#include <cuda_runtime.h>
#include <math_constants.h>

#define NQ      1024
#define LEN     50
#define NJ      974      // NQ - LEN
#define NK      100
#define KT      4        // shapelets per block (2 packed pairs)
#define KTP     2        // k-pairs
#define NTHR    128
#define RJ      8        // consecutive j per thread -> 1024 positions
#define NCHUNK  13       // 52 padded l-steps / 4
#define NWARP   4
#define ALPHA_F (-100.0f)
#define INV_LEN (1.0f / 50.0f)
#define BIGD    1.0e30f

__device__ __forceinline__ void unpack2(unsigned long long v, float& lo, float& hi) {
    asm("mov.b64 {%0, %1}, %2;" : "=f"(lo), "=f"(hi) : "l"(v));
}
// d = a*b + d, two packed fp32 lanes
__device__ __forceinline__ void ffma2(unsigned long long& d,
                                      unsigned long long a, unsigned long long b) {
    asm("fma.rn.f32x2 %0, %1, %2, %0;" : "+l"(d) : "l"(a), "l"(b));
}

__global__ __launch_bounds__(NTHR, 5)
void softmin_shapelet_kernel(const float* __restrict__ x,
                             const float* __restrict__ s,
                             float* __restrict__ out)
{
    __shared__ __align__(16) float2 dup[1088];        // {x[m], x[m]} duplicated, zero-padded
    __shared__ __align__(16) float  csA[1088];        // csA[m] = csum[m+1] (cumsum of x^2)
    __shared__ __align__(16) float2 spair[KTP][56];   // {s_2kp[l], s_2kp+1[l]}, zero-padded
    __shared__ float ssq_sh[KT];
    __shared__ float warpsum[NWARP];
    __shared__ float redmin[NWARP][KT];
    __shared__ float redsum[NWARP][KT][2];

    const int t    = threadIdx.x;
    const int n    = blockIdx.y;
    const int k0   = blockIdx.x * KT;
    const int warp = t >> 5;
    const int lane = t & 31;

    // ---- stage x: load 8 values, write duplicated pairs ----
    const float4* xg = (const float4*)(x + (size_t)n * NQ);
    float4 a0 = xg[2 * t], a1 = xg[2 * t + 1];
    float v[8] = {a0.x, a0.y, a0.z, a0.w, a1.x, a1.y, a1.z, a1.w};

    float4* dup4 = (float4*)dup;
    #pragma unroll
    for (int q = 0; q < 4; q++)
        dup4[4 * t + q] = make_float4(v[2 * q], v[2 * q], v[2 * q + 1], v[2 * q + 1]);
    if (t < 32) dup4[512 + t] = make_float4(0.f, 0.f, 0.f, 0.f);           // dup[1024..1087]
    if (t < 16) ((float4*)csA)[256 + t] = make_float4(0.f, 0.f, 0.f, 0.f); // csA[1024..1087]

    // ---- stage shapelet k-pairs, zero-padded ----
    for (int i = t; i < KTP * 56; i += NTHR) {
        int kp = i / 56, l = i - kp * 56;
        float va = (l < LEN) ? s[(size_t)(k0 + 2 * kp)     * LEN + l] : 0.0f;
        float vb = (l < LEN) ? s[(size_t)(k0 + 2 * kp + 1) * LEN + l] : 0.0f;
        spair[kp][l] = make_float2(va, vb);
    }

    // ---- per-thread prefix of x^2, then block scan ----
    float p[8];
    p[0] = v[0] * v[0];
    #pragma unroll
    for (int i = 1; i < 8; i++) p[i] = fmaf(v[i], v[i], p[i - 1]);
    float tot = p[7], inc = tot;
    #pragma unroll
    for (int off = 1; off < 32; off <<= 1) {
        float o = __shfl_up_sync(0xFFFFFFFFu, inc, off);
        if (lane >= off) inc += o;
    }
    if (lane == 31) warpsum[warp] = inc;
    __syncthreads();

    float base = 0.0f;
    #pragma unroll
    for (int w = 0; w < NWARP; w++) if (w < warp) base += warpsum[w];
    const float ex = base + inc - tot;               // csum at position 8t
    ((float4*)csA)[2 * t]     = make_float4(ex + p[0], ex + p[1], ex + p[2], ex + p[3]);
    ((float4*)csA)[2 * t + 1] = make_float4(ex + p[4], ex + p[5], ex + p[6], ex + p[7]);

    if (t < KT) {                                    // shapelet self-energy
        const int kp = t >> 1, comp = t & 1;
        float aq = 0.0f;
        #pragma unroll
        for (int l = 0; l < LEN; l++) {
            float sv = comp ? spair[kp][l].y : spair[kp][l].x;
            aq = fmaf(sv, sv, aq);
        }
        ssq_sh[t] = aq;
    }
    __syncthreads();

    // ---- sq_win BEFORE mainloop (frees p/v registers through the hot loop) ----
    float sq[RJ];
    #pragma unroll
    for (int i = 0; i < RJ; i++) {
        float ce = csA[8 * t + 49 + i];              // csum[8t+i+50]
        float cs = (i == 0) ? ex : ex + p[i - 1];    // csum[8t+i]
        sq[i] = ce - cs;                             // window energy
    }

    // ---- mainloop: all operands are aligned 64-bit SMEM pairs, zero packing ----
    unsigned long long acc2[RJ][KTP];
    #pragma unroll
    for (int jj = 0; jj < RJ; jj++)
        #pragma unroll
        for (int kp = 0; kp < KTP; kp++) acc2[jj][kp] = 0ull;

    const ulonglong2* dup2 = (const ulonglong2*)dup;
    unsigned long long d[12];                        // dup[8t+4c .. 8t+4c+11]
    {
        ulonglong2 q0 = dup2[4 * t + 0], q1 = dup2[4 * t + 1], q2 = dup2[4 * t + 2];
        ulonglong2 q3 = dup2[4 * t + 3], q4 = dup2[4 * t + 4], q5 = dup2[4 * t + 5];
        d[0] = q0.x; d[1]  = q0.y; d[2]  = q1.x; d[3]  = q1.y;
        d[4] = q2.x; d[5]  = q2.y; d[6]  = q3.x; d[7]  = q3.y;
        d[8] = q4.x; d[9]  = q4.y; d[10] = q5.x; d[11] = q5.y;
    }

    #pragma unroll
    for (int c = 0; c < NCHUNK; c++) {
        unsigned long long sd[KTP][4];
        #pragma unroll
        for (int kp = 0; kp < KTP; kp++) {
            const ulonglong2* sp = (const ulonglong2*)spair[kp];
            ulonglong2 pa = sp[2 * c], pb = sp[2 * c + 1];
            sd[kp][0] = pa.x; sd[kp][1] = pa.y; sd[kp][2] = pb.x; sd[kp][3] = pb.y;
        }
        #pragma unroll
        for (int dl = 0; dl < 4; dl++)
            #pragma unroll
            for (int jj = 0; jj < RJ; jj++)
                #pragma unroll
                for (int kp = 0; kp < KTP; kp++)
                    ffma2(acc2[jj][kp], d[jj + dl], sd[kp][dl]);
        if (c < NCHUNK - 1) {
            #pragma unroll
            for (int i = 0; i < 8; i++) d[i] = d[i + 4];
            ulonglong2 qa = dup2[4 * t + 2 * c + 6], qb = dup2[4 * t + 2 * c + 7];
            d[8] = qa.x; d[9] = qa.y; d[10] = qb.x; d[11] = qb.y;
        }
    }

    // ---- convert acc -> D exactly once (scalar, reuses acc register space) ----
    // D = (sq - 2*acc + ssq) / L ; invalid j masked with BIGD (exp underflows to 0,
    // 0*BIGD == 0, so no branches needed anywhere downstream).
    const float ssqi0 = ssq_sh[0] * INV_LEN, ssqi1 = ssq_sh[1] * INV_LEN;
    const float ssqi2 = ssq_sh[2] * INV_LEN, ssqi3 = ssq_sh[3] * INV_LEN;
    const float M2INV = -2.0f * INV_LEN;

    float D[RJ][KT];
    #pragma unroll
    for (int jj = 0; jj < RJ; jj++) {
        const bool valid = (8 * t + jj < NJ);
        const float bb = sq[jj] * INV_LEN;
        #pragma unroll
        for (int kp = 0; kp < KTP; kp++) {
            float ca, cb;
            unpack2(acc2[jj][kp], ca, cb);
            float Da = fmaf(ca, M2INV, bb + ((kp == 0) ? ssqi0 : ssqi2));
            float Db = fmaf(cb, M2INV, bb + ((kp == 0) ? ssqi1 : ssqi3));
            D[jj][2 * kp]     = valid ? Da : BIGD;
            D[jj][2 * kp + 1] = valid ? Db : BIGD;
        }
    }

    // ---- pass 1: block min per k ----
    float gmin[KT];
    {
        float m[KT];
        #pragma unroll
        for (int k = 0; k < KT; k++) {
            float mv = D[0][k];
            #pragma unroll
            for (int jj = 1; jj < RJ; jj++) mv = fminf(mv, D[jj][k]);
            #pragma unroll
            for (int off = 16; off > 0; off >>= 1)
                mv = fminf(mv, __shfl_xor_sync(0xFFFFFFFFu, mv, off));
            m[k] = mv;
            if (lane == 0) redmin[warp][k] = mv;
        }
        __syncthreads();
        #pragma unroll
        for (int k = 0; k < KT; k++) {
            float mv = redmin[0][k];
            #pragma unroll
            for (int w = 1; w < NWARP; w++) mv = fminf(mv, redmin[w][k]);
            gmin[k] = mv;
        }
    }

    // ---- pass 2: softmin sums (branch-free) ----
    float sw[KT], swd[KT];
    #pragma unroll
    for (int k = 0; k < KT; k++) { sw[k] = 0.0f; swd[k] = 0.0f; }

    #pragma unroll
    for (int jj = 0; jj < RJ; jj++) {
        #pragma unroll
        for (int k = 0; k < KT; k++) {
            float dd = D[jj][k] - gmin[k];
            float w  = __expf(ALPHA_F * dd);       // 0 exactly when dd huge
            sw[k]  += w;
            swd[k]  = fmaf(w, dd, swd[k]);         // 0*BIGD-ish = 0 since w==0
        }
    }

    #pragma unroll
    for (int k = 0; k < KT; k++) {
        #pragma unroll
        for (int off = 16; off > 0; off >>= 1) {
            sw[k]  += __shfl_xor_sync(0xFFFFFFFFu, sw[k],  off);
            swd[k] += __shfl_xor_sync(0xFFFFFFFFu, swd[k], off);
        }
        if (lane == 0) { redsum[warp][k][0] = sw[k]; redsum[warp][k][1] = swd[k]; }
    }
    __syncthreads();

    if (t < KT) {
        float SW = 0.0f, SWD = 0.0f;
        #pragma unroll
        for (int w = 0; w < NWARP; w++) {
            SW  += redsum[w][t][0];
            SWD += redsum[w][t][1];
        }
        out[(size_t)n * NK + k0 + t] = SWD / SW;
    }
}

extern "C" void kernel_launch(void* const* d_in, const int* in_sizes, int n_in,
                              void* d_out, int out_size)
{
    const float* x = (const float*)d_in[0];   // (512, 1024)
    const float* s = (const float*)d_in[1];   // (100, 50)
    float* out = (float*)d_out;               // (512, 100)

    dim3 grid(NK / KT, 512);                  // (25, 512)
    softmin_shapelet_kernel<<<grid, NTHR>>>(x, s, out);
}

// round 11
// speedup vs baseline: 3.9579x; 1.1265x over previous
#include <cuda_runtime.h>
#include <math_constants.h>

#define NQ      1024
#define LEN     50
#define NJ      974      // NQ - LEN
#define NK      100
#define KT      4        // shapelets per block (2 packed pairs)
#define KTP     2        // k-pairs
#define NTHR    128
#define RJ      8        // consecutive j per thread -> 1024 positions
#define NCHUNK  13       // 52 padded l-steps / 4
#define NWARP   4
#define ALPHA_F (-100.0f)
#define INV_LEN (1.0f / 50.0f)
#define BIGD    1.0e30f

__device__ __forceinline__ void unpack2(unsigned long long v, float& lo, float& hi) {
    asm("mov.b64 {%0, %1}, %2;" : "=f"(lo), "=f"(hi) : "l"(v));
}
// d = a*b + d, two packed fp32 lanes
__device__ __forceinline__ void ffma2(unsigned long long& d,
                                      unsigned long long a, unsigned long long b) {
    asm("fma.rn.f32x2 %0, %1, %2, %0;" : "+l"(d) : "l"(a), "l"(b));
}
// 16B-slot swizzle: permutes slots within each 128B block -> conflict-free
// for the 64B-lane-stride access pattern of the mainloop.
__device__ __forceinline__ int sw(int i) { return i ^ ((i >> 3) & 7); }

__global__ __launch_bounds__(NTHR, 5)
void softmin_shapelet_kernel(const float* __restrict__ x,
                             const float* __restrict__ s,
                             float* __restrict__ out)
{
    __shared__ __align__(16) float2 dup[1088];        // {x[m],x[m]} duplicated, SWIZZLED slots
    __shared__ __align__(16) float  csA[1088];        // csA[m] = csum[m+1] (cumsum of x^2)
    __shared__ __align__(16) float2 spair[KTP][56];   // {s_2kp[l], s_2kp+1[l]}, zero-padded
    __shared__ float ssq_sh[KT];
    __shared__ float warpsum[NWARP];
    __shared__ float redmin[NWARP][KT];
    __shared__ float redsum[NWARP][KT][2];

    const int t    = threadIdx.x;
    const int n    = blockIdx.y;
    const int k0   = blockIdx.x * KT;
    const int warp = t >> 5;
    const int lane = t & 31;

    // ---- stage x: load 8 values, write duplicated pairs (swizzled slots) ----
    const float4* xg = (const float4*)(x + (size_t)n * NQ);
    float4 a0 = xg[2 * t], a1 = xg[2 * t + 1];
    float v[8] = {a0.x, a0.y, a0.z, a0.w, a1.x, a1.y, a1.z, a1.w};

    float4* dup4 = (float4*)dup;                      // 16B slots, 544 total
    #pragma unroll
    for (int q = 0; q < 4; q++)
        dup4[sw(4 * t + q)] = make_float4(v[2 * q], v[2 * q], v[2 * q + 1], v[2 * q + 1]);
    if (t < 32) dup4[sw(512 + t)] = make_float4(0.f, 0.f, 0.f, 0.f);      // dup[1024..1087]
    if (t < 16) ((float4*)csA)[256 + t] = make_float4(0.f, 0.f, 0.f, 0.f); // csA[1024..1087]

    // ---- stage shapelet k-pairs, zero-padded ----
    for (int i = t; i < KTP * 56; i += NTHR) {
        int kp = i / 56, l = i - kp * 56;
        float va = (l < LEN) ? s[(size_t)(k0 + 2 * kp)     * LEN + l] : 0.0f;
        float vb = (l < LEN) ? s[(size_t)(k0 + 2 * kp + 1) * LEN + l] : 0.0f;
        spair[kp][l] = make_float2(va, vb);
    }

    // ---- per-thread prefix of x^2, then block scan ----
    float p[8];
    p[0] = v[0] * v[0];
    #pragma unroll
    for (int i = 1; i < 8; i++) p[i] = fmaf(v[i], v[i], p[i - 1]);
    float tot = p[7], inc = tot;
    #pragma unroll
    for (int off = 1; off < 32; off <<= 1) {
        float o = __shfl_up_sync(0xFFFFFFFFu, inc, off);
        if (lane >= off) inc += o;
    }
    if (lane == 31) warpsum[warp] = inc;
    __syncthreads();

    float base = 0.0f;
    #pragma unroll
    for (int w = 0; w < NWARP; w++) if (w < warp) base += warpsum[w];
    const float ex = base + inc - tot;               // csum at position 8t
    ((float4*)csA)[2 * t]     = make_float4(ex + p[0], ex + p[1], ex + p[2], ex + p[3]);
    ((float4*)csA)[2 * t + 1] = make_float4(ex + p[4], ex + p[5], ex + p[6], ex + p[7]);

    if (t < KT) {                                    // shapelet self-energy
        const int kp = t >> 1, comp = t & 1;
        float aq = 0.0f;
        #pragma unroll
        for (int l = 0; l < LEN; l++) {
            float sv = comp ? spair[kp][l].y : spair[kp][l].x;
            aq = fmaf(sv, sv, aq);
        }
        ssq_sh[t] = aq;
    }
    __syncthreads();

    // ---- sq_win BEFORE mainloop (frees p/v registers through the hot loop) ----
    float sq[RJ];
    #pragma unroll
    for (int i = 0; i < RJ; i++) {
        float ce = csA[8 * t + 49 + i];              // csum[8t+i+50]
        float cs = (i == 0) ? ex : ex + p[i - 1];    // csum[8t+i]
        sq[i] = ce - cs;                             // window energy
    }

    // ---- mainloop: aligned 64-bit SMEM pair operands, swizzled x stream ----
    unsigned long long acc2[RJ][KTP];
    #pragma unroll
    for (int jj = 0; jj < RJ; jj++)
        #pragma unroll
        for (int kp = 0; kp < KTP; kp++) acc2[jj][kp] = 0ull;

    const ulonglong2* dup2 = (const ulonglong2*)dup;
    unsigned long long d[12];                        // dup[8t+4c .. 8t+4c+11]
    {
        ulonglong2 q0 = dup2[sw(4 * t + 0)], q1 = dup2[sw(4 * t + 1)], q2 = dup2[sw(4 * t + 2)];
        ulonglong2 q3 = dup2[sw(4 * t + 3)], q4 = dup2[sw(4 * t + 4)], q5 = dup2[sw(4 * t + 5)];
        d[0] = q0.x; d[1]  = q0.y; d[2]  = q1.x; d[3]  = q1.y;
        d[4] = q2.x; d[5]  = q2.y; d[6]  = q3.x; d[7]  = q3.y;
        d[8] = q4.x; d[9]  = q4.y; d[10] = q5.x; d[11] = q5.y;
    }

    #pragma unroll
    for (int c = 0; c < NCHUNK; c++) {
        unsigned long long sd[KTP][4];
        #pragma unroll
        for (int kp = 0; kp < KTP; kp++) {
            const ulonglong2* sp = (const ulonglong2*)spair[kp];
            ulonglong2 pa = sp[2 * c], pb = sp[2 * c + 1];   // warp-broadcast, conflict-free
            sd[kp][0] = pa.x; sd[kp][1] = pa.y; sd[kp][2] = pb.x; sd[kp][3] = pb.y;
        }
        #pragma unroll
        for (int dl = 0; dl < 4; dl++)
            #pragma unroll
            for (int jj = 0; jj < RJ; jj++)
                #pragma unroll
                for (int kp = 0; kp < KTP; kp++)
                    ffma2(acc2[jj][kp], d[jj + dl], sd[kp][dl]);
        if (c < NCHUNK - 1) {
            #pragma unroll
            for (int i = 0; i < 8; i++) d[i] = d[i + 4];
            ulonglong2 qa = dup2[sw(4 * t + 2 * c + 6)], qb = dup2[sw(4 * t + 2 * c + 7)];
            d[8] = qa.x; d[9] = qa.y; d[10] = qb.x; d[11] = qb.y;
        }
    }

    // ---- convert acc -> D exactly once; invalid j masked with BIGD ----
    const float ssqi0 = ssq_sh[0] * INV_LEN, ssqi1 = ssq_sh[1] * INV_LEN;
    const float ssqi2 = ssq_sh[2] * INV_LEN, ssqi3 = ssq_sh[3] * INV_LEN;
    const float M2INV = -2.0f * INV_LEN;

    float D[RJ][KT];
    #pragma unroll
    for (int jj = 0; jj < RJ; jj++) {
        const bool valid = (8 * t + jj < NJ);
        const float bb = sq[jj] * INV_LEN;
        #pragma unroll
        for (int kp = 0; kp < KTP; kp++) {
            float ca, cb;
            unpack2(acc2[jj][kp], ca, cb);
            float Da = fmaf(ca, M2INV, bb + ((kp == 0) ? ssqi0 : ssqi2));
            float Db = fmaf(cb, M2INV, bb + ((kp == 0) ? ssqi1 : ssqi3));
            D[jj][2 * kp]     = valid ? Da : BIGD;
            D[jj][2 * kp + 1] = valid ? Db : BIGD;
        }
    }

    // ---- pass 1: block min per k ----
    float gmin[KT];
    {
        #pragma unroll
        for (int k = 0; k < KT; k++) {
            float mv = D[0][k];
            #pragma unroll
            for (int jj = 1; jj < RJ; jj++) mv = fminf(mv, D[jj][k]);
            #pragma unroll
            for (int off = 16; off > 0; off >>= 1)
                mv = fminf(mv, __shfl_xor_sync(0xFFFFFFFFu, mv, off));
            if (lane == 0) redmin[warp][k] = mv;
        }
        __syncthreads();
        #pragma unroll
        for (int k = 0; k < KT; k++) {
            float mv = redmin[0][k];
            #pragma unroll
            for (int w = 1; w < NWARP; w++) mv = fminf(mv, redmin[w][k]);
            gmin[k] = mv;
        }
    }

    // ---- pass 2: softmin sums (branch-free) ----
    float swt[KT], swd[KT];
    #pragma unroll
    for (int k = 0; k < KT; k++) { swt[k] = 0.0f; swd[k] = 0.0f; }

    #pragma unroll
    for (int jj = 0; jj < RJ; jj++) {
        #pragma unroll
        for (int k = 0; k < KT; k++) {
            float dd = D[jj][k] - gmin[k];
            float w  = __expf(ALPHA_F * dd);       // 0 exactly when dd huge
            swt[k] += w;
            swd[k]  = fmaf(w, dd, swd[k]);
        }
    }

    #pragma unroll
    for (int k = 0; k < KT; k++) {
        #pragma unroll
        for (int off = 16; off > 0; off >>= 1) {
            swt[k] += __shfl_xor_sync(0xFFFFFFFFu, swt[k], off);
            swd[k] += __shfl_xor_sync(0xFFFFFFFFu, swd[k], off);
        }
        if (lane == 0) { redsum[warp][k][0] = swt[k]; redsum[warp][k][1] = swd[k]; }
    }
    __syncthreads();

    if (t < KT) {
        float SW = 0.0f, SWD = 0.0f;
        #pragma unroll
        for (int w = 0; w < NWARP; w++) {
            SW  += redsum[w][t][0];
            SWD += redsum[w][t][1];
        }
        out[(size_t)n * NK + k0 + t] = SWD / SW;
    }
}

extern "C" void kernel_launch(void* const* d_in, const int* in_sizes, int n_in,
                              void* d_out, int out_size)
{
    const float* x = (const float*)d_in[0];   // (512, 1024)
    const float* s = (const float*)d_in[1];   // (100, 50)
    float* out = (float*)d_out;               // (512, 100)

    dim3 grid(NK / KT, 512);                  // (25, 512)
    softmin_shapelet_kernel<<<grid, NTHR>>>(x, s, out);
}